// round 7
// baseline (speedup 1.0000x reference)
#include <cuda_runtime.h>
#include <cuda_bf16.h>
#include <cstdint>

// Problem constants
#define T_SEQ 512
#define B_SZ  64
#define E_SZ  512
#define G3E   1536
#define M_ROWS (T_SEQ * B_SZ)

// ---------------- device scratch ----------------
__device__ float g_x[T_SEQ * B_SZ * E_SZ];
__device__ float g_xproj[T_SEQ * B_SZ * G3E];
__device__ float g_h[B_SZ * E_SZ];
__device__ unsigned g_ctr[256];          // per-(CTA, bg-in-pair) monotonic counters

// ---------------- f32x2 helpers ----------------
__device__ __forceinline__ void fma2(unsigned long long& d, unsigned long long a,
                                     unsigned long long b) {
    asm("fma.rn.f32x2 %0, %1, %2, %3;" : "=l"(d) : "l"(a), "l"(b), "l"(d));
}
__device__ __forceinline__ float f32x2_sum(unsigned long long v) {
    return __uint_as_float((unsigned)v) + __uint_as_float((unsigned)(v >> 32));
}
__device__ __forceinline__ unsigned long long dup2(float x) {
    unsigned long long r; unsigned u = __float_as_uint(x);
    asm("mov.b64 %0, {%1, %1};" : "=l"(r) : "r"(u));
    return r;
}

// ---------------- counter primitives ----------------
__device__ __forceinline__ void ctr_release_add(unsigned* ctr) {
    asm volatile("red.release.gpu.global.add.u32 [%0], %1;" :: "l"(ctr), "r"(1u) : "memory");
}
__device__ __forceinline__ void ctr_wait(unsigned* ctr, unsigned target) {
    unsigned cur;
    do {
        asm volatile("ld.acquire.gpu.u32 %0, [%1];" : "=r"(cur) : "l"(ctr) : "memory");
    } while ((int)(cur - target) < 0);
}

// ---------------- cp.async helpers ----------------
__device__ __forceinline__ void cp_async4(unsigned dst, const void* src) {
    asm volatile("cp.async.ca.shared.global [%0], [%1], 4;" :: "r"(dst), "l"(src));
}

// ---------------- embedding gather (+ counter reset) ----------------
__global__ void embed_kernel(const int* __restrict__ idx,
                             const float* __restrict__ emb,
                             float* __restrict__ out) {
    if (blockIdx.x == 0 && threadIdx.x < 256) g_ctr[threadIdx.x] = 0u;
    int i = blockIdx.x * blockDim.x + threadIdx.x;
    const int total = T_SEQ * B_SZ * (E_SZ / 4);
    if (i >= total) return;
    int row = i >> 7;
    int col = i & 127;
    int tok = idx[row];
    reinterpret_cast<float4*>(out)[i] =
        reinterpret_cast<const float4*>(emb)[(size_t)tok * 128 + col];
}

// ---------------- fp32 GEMM with cp.async double buffering ----------------
#define BM 128
#define BN 128
#define BK 16
#define NKT (E_SZ / BK)      // 32 k-tiles

__global__ __launch_bounds__(256) void gemm_nt_bias(
    const float* __restrict__ A, const float* __restrict__ Bm,
    const float* __restrict__ bias, float* __restrict__ C,
    int M, int N, int K) {
    __shared__ float As[2][BK][BM];
    __shared__ float Bs[2][BK][BN];

    const int tid = threadIdx.x;
    const int bm = blockIdx.y * BM;
    const int bn = blockIdx.x * BN;
    const int tx = tid & 15;
    const int ty = tid >> 4;

    unsigned long long acc2[4][8];
#pragma unroll
    for (int i = 0; i < 4; i++)
#pragma unroll
        for (int j = 0; j < 8; j++) acc2[i][j] = 0ULL;

    // async tile loader: 4B copies with on-the-fly transpose into [k][row]
    auto load_tile = [&](int kt, int buf) {
        int kb = kt * BK;
#pragma unroll
        for (int j = 0; j < 8; j++) {
            int idx = j * 256 + tid;
            int row = idx >> 4, k = idx & 15;
            cp_async4((unsigned)__cvta_generic_to_shared(&As[buf][k][row]),
                      &A[(size_t)(bm + row) * K + kb + k]);
        }
#pragma unroll
        for (int j = 0; j < 8; j++) {
            int idx = j * 256 + tid;
            int row = idx >> 4, k = idx & 15;
            cp_async4((unsigned)__cvta_generic_to_shared(&Bs[buf][k][row]),
                      &Bm[(size_t)(bn + row) * K + kb + k]);
        }
        asm volatile("cp.async.commit_group;");
    };

    load_tile(0, 0);

    for (int i = 0; i < NKT; i++) {
        if (i + 1 < NKT) {
            load_tile(i + 1, (i + 1) & 1);
            asm volatile("cp.async.wait_group 1;");
        } else {
            asm volatile("cp.async.wait_group 0;");
        }
        __syncthreads();

        const int buf = i & 1;
#pragma unroll
        for (int k = 0; k < BK; k++) {
            ulonglong2 aq0 = *reinterpret_cast<const ulonglong2*>(&As[buf][k][ty * 8]);
            ulonglong2 aq1 = *reinterpret_cast<const ulonglong2*>(&As[buf][k][ty * 8 + 4]);
            float4 b0 = *reinterpret_cast<const float4*>(&Bs[buf][k][tx * 8]);
            float4 b1 = *reinterpret_cast<const float4*>(&Bs[buf][k][tx * 8 + 4]);
            unsigned long long ap[4] = {aq0.x, aq0.y, aq1.x, aq1.y};
            unsigned long long bd[8] = {dup2(b0.x), dup2(b0.y), dup2(b0.z), dup2(b0.w),
                                        dup2(b1.x), dup2(b1.y), dup2(b1.z), dup2(b1.w)};
#pragma unroll
            for (int ip = 0; ip < 4; ip++)
#pragma unroll
                for (int j = 0; j < 8; j++) fma2(acc2[ip][j], ap[ip], bd[j]);
        }
        __syncthreads();
    }

    float bv[8];
    {
        float4 bias0 = *reinterpret_cast<const float4*>(&bias[bn + tx * 8]);
        float4 bias1 = *reinterpret_cast<const float4*>(&bias[bn + tx * 8 + 4]);
        bv[0] = bias0.x; bv[1] = bias0.y; bv[2] = bias0.z; bv[3] = bias0.w;
        bv[4] = bias1.x; bv[5] = bias1.y; bv[6] = bias1.z; bv[7] = bias1.w;
    }
#pragma unroll
    for (int ip = 0; ip < 4; ip++) {
        float lo[8], hi[8];
#pragma unroll
        for (int j = 0; j < 8; j++) {
            lo[j] = __uint_as_float((unsigned)acc2[ip][j]) + bv[j];
            hi[j] = __uint_as_float((unsigned)(acc2[ip][j] >> 32)) + bv[j];
        }
        int row0 = bm + ty * 8 + 2 * ip;
        float* cp0 = &C[(size_t)row0 * N + bn + tx * 8];
        float* cp1 = cp0 + N;
        *reinterpret_cast<float4*>(cp0)     = make_float4(lo[0], lo[1], lo[2], lo[3]);
        *reinterpret_cast<float4*>(cp0 + 4) = make_float4(lo[4], lo[5], lo[6], lo[7]);
        *reinterpret_cast<float4*>(cp1)     = make_float4(hi[0], hi[1], hi[2], hi[3]);
        *reinterpret_cast<float4*>(cp1 + 4) = make_float4(hi[4], hi[5], hi[6], hi[7]);
    }
}

// ---------------- persistent GRU recurrence: 2 bgs interleaved per CTA ----------------
// 128 CTAs = 4 pairs (bgs 2p, 2p+1) x 32 e-groups of 16 cols. 256 threads.
// Weights (48 rows x 512, shared by both bgs) in smem. Per global step:
// phase A (bg 2p) then phase B (bg 2p+1); cross-SM propagation of each phase's
// h hides under the other phase's compute. h pre-staged one phase ahead.
// Lane = (eL 0..15, ks 0..1): e-column ebase+eL, k half-slice [64w+32ks, +32).
#define RGRID 128
#define WSTR 516
#define WR2 48
#define SM_HA (WR2 * WSTR)              // 24768
#define SM_HB (SM_HA + 4096)
#define SM_PT (SM_HB + 4096)
#define RSMEM_FLOATS (SM_PT + 9216)     // 42176
#define RSMEM_BYTES (RSMEM_FLOATS * 4)  // 168704 B

#define STAGE(stripe, bg) do {                                                 \
    const float4* hb4 = reinterpret_cast<const float4*>(hbuf);                 \
    _Pragma("unroll")                                                          \
    for (int i_ = 0; i_ < 4; i_++) {                                           \
        int f_ = jg + i_ * 32; int b_ = f_ >> 4, c4_ = f_ & 15;                \
        *reinterpret_cast<float4*>(&(stripe)[b_ * 64 + c4_ * 4]) =             \
            hb4[((bg) * 8 + b_) * 128 + 16 * w + c4_];                         \
    }                                                                          \
    __syncwarp();                                                              \
} while (0)

#define DOT(stripe) do {                                                       \
    _Pragma("unroll")                                                          \
    for (int b_ = 0; b_ < 8; b_++) { a0[b_] = 0ULL; a1[b_] = 0ULL; a2[b_] = 0ULL; } \
    _Pragma("unroll 4")                                                        \
    for (int kk_ = 0; kk_ < 8; kk_++) {                                        \
        int kg_ = koff + kk_ * 4;                                              \
        int kl_ = ks * 32 + kk_ * 4;                                           \
        ulonglong2 w0_ = *reinterpret_cast<const ulonglong2*>(wp0 + kg_);      \
        ulonglong2 w1_ = *reinterpret_cast<const ulonglong2*>(wp1 + kg_);      \
        ulonglong2 w2_ = *reinterpret_cast<const ulonglong2*>(wp2 + kg_);      \
        _Pragma("unroll")                                                      \
        for (int b_ = 0; b_ < 8; b_++) {                                       \
            ulonglong2 h2_ = *reinterpret_cast<const ulonglong2*>((stripe) + b_ * 64 + kl_); \
            fma2(a0[b_], h2_.x, w0_.x); fma2(a0[b_], h2_.y, w0_.y);            \
            fma2(a1[b_], h2_.x, w1_.x); fma2(a1[b_], h2_.y, w1_.y);            \
            fma2(a2[b_], h2_.x, w2_.x); fma2(a2[b_], h2_.y, w2_.y);            \
        }                                                                      \
    }                                                                          \
} while (0)

#define STORE_PART() do {                                                      \
    _Pragma("unroll")                                                          \
    for (int b_ = 0; b_ < 8; b_++) {                                           \
        sh_pt[((w * 3 + 0) * 8 + b_) * 48 + jg] = f32x2_sum(a0[b_]);           \
        sh_pt[((w * 3 + 1) * 8 + b_) * 48 + jg] = f32x2_sum(a1[b_]);           \
        sh_pt[((w * 3 + 2) * 8 + b_) * 48 + jg] = f32x2_sum(a2[b_]);           \
    }                                                                          \
} while (0)

#define REDUCE_GATES(xr_, xz_, xn_, hprev_, len_, bglob_, hnew_) do {          \
    float s0_ = 0.f, s1_ = 0.f, s2_ = 0.f;                                     \
    _Pragma("unroll")                                                          \
    for (int ww_ = 0; ww_ < 8; ww_++) {                                        \
        _Pragma("unroll")                                                      \
        for (int kq_ = 0; kq_ < 2; kq_++) {                                    \
            int o_ = kq_ * 16 + ee;                                            \
            s0_ += sh_pt[((ww_ * 3 + 0) * 8 + bb) * 48 + o_];                  \
            s1_ += sh_pt[((ww_ * 3 + 1) * 8 + bb) * 48 + o_];                  \
            s2_ += sh_pt[((ww_ * 3 + 2) * 8 + bb) * 48 + o_];                  \
        }                                                                      \
    }                                                                          \
    float hr_ = s0_ + bh0, hz_ = s1_ + bh1, hn_ = s2_ + bh2;                   \
    float r_ = __frcp_rn(1.f + __expf(-((xr_) + hr_)));                        \
    float z_ = __frcp_rn(1.f + __expf(-((xz_) + hz_)));                        \
    float te_ = __expf(2.f * ((xn_) + r_ * hn_));                              \
    float n_ = (te_ - 1.f) * __frcp_rn(te_ + 1.f);                             \
    bool m_ = (t < (len_));                                                    \
    (hnew_) = m_ ? ((1.f - z_) * n_ + z_ * (hprev_)) : (hprev_);               \
    (hprev_) = (hnew_);                                                        \
    hbuf[(bglob_) * E_SZ + ebase + ee] = (hnew_);                              \
    ymask = m_;                                                                \
} while (0)

__global__ __launch_bounds__(256, 1) void gru_recur_kernel(
    const float* __restrict__ xproj,
    const float* __restrict__ Whh,
    const float* __restrict__ bhh,
    const int* __restrict__ lens,
    float* __restrict__ hbuf,
    float* __restrict__ ybuf,
    float* __restrict__ finals,
    int epoch)
{
    extern __shared__ float smem[];
    float* sh_w  = smem;
    float* sh_hA = smem + SM_HA;
    float* sh_hB = smem + SM_HB;
    float* sh_pt = smem + SM_PT;

    const int tid = threadIdx.x;
    const int cta = blockIdx.x;
    const int p  = cta >> 5;          // pair 0..3
    const int eg = cta & 31;          // e-group 0..31
    const int ebase = eg * 16;
    const int w = tid >> 5;
    const int jg = tid & 31;
    const int eL = jg & 15;
    const int ks = jg >> 4;
    const int bgA = 2 * p, bgB = 2 * p + 1;

    // load 48 weight rows (row j = eL*3 + gate), float4, stride WSTR
    for (int idx = tid; idx < WR2 * (E_SZ / 4); idx += 256) {
        int j = idx >> 7;
        int kq = (idx & 127) << 2;
        int el = j / 3, g = j - el * 3;
        *reinterpret_cast<float4*>(&sh_w[j * WSTR + kq]) =
            *reinterpret_cast<const float4*>(&Whh[(size_t)(g * E_SZ + ebase + el) * E_SZ + kq]);
    }

    // gate-thread (tid < 128) setup
    int bb = 0, ee = 0, bglobA = 0, bglobB = 0, lenA = 0, lenB = 0;
    float bh0 = 0.f, bh1 = 0.f, bh2 = 0.f;
    if (tid < 128) {
        bb = tid >> 4; ee = tid & 15;
        bglobA = bgA * 8 + bb; bglobB = bgB * 8 + bb;
        bh0 = bhh[0 * E_SZ + ebase + ee];
        bh1 = bhh[1 * E_SZ + ebase + ee];
        bh2 = bhh[2 * E_SZ + ebase + ee];
        lenA = lens[bglobA]; lenB = lens[bglobB];
        hbuf[bglobA * E_SZ + ebase + ee] = 0.f;
        hbuf[bglobB * E_SZ + ebase + ee] = 0.f;
    }
    __syncthreads();
    unsigned* myc = &g_ctr[cta * 2];
    if (tid == 0) { ctr_release_add(&myc[0]); ctr_release_add(&myc[1]); }

    const unsigned base = (unsigned)epoch * (T_SEQ + 1);
    // this warp's producer counters (4 CTAs cover its 64 h-columns; lane polls one)
    unsigned* cA = &g_ctr[((p << 5) + 4 * w + (jg & 3)) * 2 + 0];
    unsigned* cB = cA + 1;

    const float* wp0 = sh_w + (eL * 3 + 0) * WSTR;
    const float* wp1 = wp0 + WSTR;
    const float* wp2 = wp1 + WSTR;
    const int koff = w * 64 + ks * 32;
    float* stA = sh_hA + w * 512;
    float* stB = sh_hB + w * 512;

    unsigned long long a0[8], a1[8], a2[8];
    float hprevA = 0.f, hprevB = 0.f, hnewA = 0.f, hnewB = 0.f;
    float xrA = 0.f, xzA = 0.f, xnA = 0.f, xrB = 0.f, xzB = 0.f, xnB = 0.f;
    bool ymask = false;

    // pre-stage A(0)
    ctr_wait(cA, base + 1);
    __syncwarp();
    STAGE(stA, bgA);

    for (int t = 0; t < T_SEQ; t++) {
        // xp for phase A (overlaps dot A)
        if (tid < 128) {
            const float* xp = xproj + ((size_t)t * B_SZ + bglobA) * G3E + ebase + ee;
            xrA = xp[0]; xzA = xp[E_SZ]; xnA = xp[2 * E_SZ];
        }

        DOT(stA);
        __syncthreads();

        // wait + stage B(t): B's h(t) was published at the end of step t-1
        ctr_wait(cB, base + 1 + (unsigned)t);
        __syncwarp();
        STAGE(stB, bgB);

        STORE_PART();
        __syncthreads();
        if (tid < 128) REDUCE_GATES(xrA, xzA, xnA, hprevA, lenA, bglobA, hnewA);
        __syncthreads();
        if (tid == 0) ctr_release_add(&myc[0]);
        if (tid < 128) {
            ybuf[((size_t)t * B_SZ + bglobA) * E_SZ + ebase + ee] = ymask ? hnewA : 0.f;
            const float* xp = xproj + ((size_t)t * B_SZ + bglobB) * G3E + ebase + ee;
            xrB = xp[0]; xzB = xp[E_SZ]; xnB = xp[2 * E_SZ];
        }

        DOT(stB);
        __syncthreads();

        // pre-stage A(t+1): A's h(t+1) was published in phase A of this step
        if (t + 1 < T_SEQ) {
            ctr_wait(cA, base + 2 + (unsigned)t);
            __syncwarp();
            STAGE(stA, bgA);
        }

        STORE_PART();
        __syncthreads();
        if (tid < 128) REDUCE_GATES(xrB, xzB, xnB, hprevB, lenB, bglobB, hnewB);
        __syncthreads();
        if (tid == 0) ctr_release_add(&myc[1]);
        if (tid < 128)
            ybuf[((size_t)t * B_SZ + bglobB) * E_SZ + ebase + ee] = ymask ? hnewB : 0.f;
    }

    if (tid < 128) {
        finals[bglobA * E_SZ + ebase + ee] = hprevA;
        finals[bglobB * E_SZ + ebase + ee] = hprevB;
    }
}

// ---------------- launch ----------------
extern "C" void kernel_launch(void* const* d_in, const int* in_sizes, int n_in,
                              void* d_out, int out_size) {
    const int*   input_batch = (const int*)d_in[0];
    const int*   lens        = (const int*)d_in[1];
    const float* emb         = (const float*)d_in[2];
    const float* W_ih        = (const float*)d_in[3];
    const float* W_hh        = (const float*)d_in[4];
    const float* b_ih        = (const float*)d_in[5];
    const float* b_hh        = (const float*)d_in[6];
    float* out = (float*)d_out;

    void* p;
    cudaGetSymbolAddress(&p, g_x);     float* gx  = (float*)p;
    cudaGetSymbolAddress(&p, g_xproj); float* gxp = (float*)p;
    cudaGetSymbolAddress(&p, g_h);     float* gh  = (float*)p;

    cudaFuncSetAttribute(gru_recur_kernel,
                         cudaFuncAttributeMaxDynamicSharedMemorySize, RSMEM_BYTES);

    const int M = M_ROWS;
    const size_t out_x_elems = (size_t)T_SEQ * B_SZ * E_SZ;
    float* finals0 = out + out_x_elems;
    float* finals1 = out + out_x_elems + B_SZ * E_SZ;

    {
        int total = T_SEQ * B_SZ * (E_SZ / 4);
        embed_kernel<<<(total + 255) / 256, 256>>>(input_batch, emb, gx);
    }
    gemm_nt_bias<<<dim3(G3E / BN, M / BM), 256>>>(gx, W_ih, b_ih, gxp, M, G3E, E_SZ);
    gru_recur_kernel<<<RGRID, 256, RSMEM_BYTES>>>(gxp, W_hh, b_hh, lens, gh, gx, finals0, 0);
    gemm_nt_bias<<<dim3(G3E / BN, M / BM), 256>>>(gx, W_ih + (size_t)G3E * E_SZ,
                                                  b_ih + G3E, gxp, M, G3E, E_SZ);
    gru_recur_kernel<<<RGRID, 256, RSMEM_BYTES>>>(gxp, W_hh + (size_t)G3E * E_SZ,
                                                  b_hh + G3E, lens, gh, out, finals1, 1);
}

// round 8
// speedup vs baseline: 1.0282x; 1.0282x over previous
#include <cuda_runtime.h>
#include <cuda_bf16.h>
#include <cstdint>

// Problem constants
#define T_SEQ 512
#define B_SZ  64
#define E_SZ  512
#define G3E   1536
#define M_ROWS (T_SEQ * B_SZ)

// ---------------- device scratch ----------------
__device__ float g_x[T_SEQ * B_SZ * E_SZ];
__device__ float g_xproj[T_SEQ * B_SZ * G3E];
__device__ float g_h[B_SZ * E_SZ];
__device__ unsigned g_ctr[256];          // per-(CTA, bg-in-pair) monotonic counters

// ---------------- f32x2 helpers ----------------
__device__ __forceinline__ void fma2(unsigned long long& d, unsigned long long a,
                                     unsigned long long b) {
    asm("fma.rn.f32x2 %0, %1, %2, %3;" : "=l"(d) : "l"(a), "l"(b), "l"(d));
}
__device__ __forceinline__ float f32x2_sum(unsigned long long v) {
    return __uint_as_float((unsigned)v) + __uint_as_float((unsigned)(v >> 32));
}
__device__ __forceinline__ unsigned long long dup2(float x) {
    unsigned long long r; unsigned u = __float_as_uint(x);
    asm("mov.b64 %0, {%1, %1};" : "=l"(r) : "r"(u));
    return r;
}

// ---------------- counter primitives ----------------
__device__ __forceinline__ void ctr_release_add(unsigned* ctr) {
    asm volatile("red.release.gpu.global.add.u32 [%0], %1;" :: "l"(ctr), "r"(1u) : "memory");
}
__device__ __forceinline__ void ctr_wait(unsigned* ctr, unsigned target) {
    unsigned cur;
    do {
        asm volatile("ld.acquire.gpu.u32 %0, [%1];" : "=r"(cur) : "l"(ctr) : "memory");
    } while ((int)(cur - target) < 0);
}

// ---------------- cp.async helpers ----------------
__device__ __forceinline__ void cp_async4(unsigned dst, const void* src) {
    asm volatile("cp.async.ca.shared.global [%0], [%1], 4;" :: "r"(dst), "l"(src));
}

// ---------------- embedding gather (+ counter reset) ----------------
__global__ void embed_kernel(const int* __restrict__ idx,
                             const float* __restrict__ emb,
                             float* __restrict__ out) {
    if (blockIdx.x == 0 && threadIdx.x < 256) g_ctr[threadIdx.x] = 0u;
    int i = blockIdx.x * blockDim.x + threadIdx.x;
    const int total = T_SEQ * B_SZ * (E_SZ / 4);
    if (i >= total) return;
    int row = i >> 7;
    int col = i & 127;
    int tok = idx[row];
    reinterpret_cast<float4*>(out)[i] =
        reinterpret_cast<const float4*>(emb)[(size_t)tok * 128 + col];
}

// ---------------- fp32 GEMM with cp.async double buffering ----------------
#define BM 128
#define BN 128
#define BK 16
#define NKT (E_SZ / BK)      // 32 k-tiles

__global__ __launch_bounds__(256) void gemm_nt_bias(
    const float* __restrict__ A, const float* __restrict__ Bm,
    const float* __restrict__ bias, float* __restrict__ C,
    int M, int N, int K) {
    __shared__ float As[2][BK][BM];
    __shared__ float Bs[2][BK][BN];

    const int tid = threadIdx.x;
    const int bm = blockIdx.y * BM;
    const int bn = blockIdx.x * BN;
    const int tx = tid & 15;
    const int ty = tid >> 4;

    unsigned long long acc2[4][8];
#pragma unroll
    for (int i = 0; i < 4; i++)
#pragma unroll
        for (int j = 0; j < 8; j++) acc2[i][j] = 0ULL;

    // async tile loader: 4B copies with on-the-fly transpose into [k][row]
    auto load_tile = [&](int kt, int buf) {
        int kb = kt * BK;
#pragma unroll
        for (int j = 0; j < 8; j++) {
            int idx = j * 256 + tid;
            int row = idx >> 4, k = idx & 15;
            cp_async4((unsigned)__cvta_generic_to_shared(&As[buf][k][row]),
                      &A[(size_t)(bm + row) * K + kb + k]);
        }
#pragma unroll
        for (int j = 0; j < 8; j++) {
            int idx = j * 256 + tid;
            int row = idx >> 4, k = idx & 15;
            cp_async4((unsigned)__cvta_generic_to_shared(&Bs[buf][k][row]),
                      &Bm[(size_t)(bn + row) * K + kb + k]);
        }
        asm volatile("cp.async.commit_group;");
    };

    load_tile(0, 0);

    for (int i = 0; i < NKT; i++) {
        if (i + 1 < NKT) {
            load_tile(i + 1, (i + 1) & 1);
            asm volatile("cp.async.wait_group 1;");
        } else {
            asm volatile("cp.async.wait_group 0;");
        }
        __syncthreads();

        const int buf = i & 1;
#pragma unroll
        for (int k = 0; k < BK; k++) {
            ulonglong2 aq0 = *reinterpret_cast<const ulonglong2*>(&As[buf][k][ty * 8]);
            ulonglong2 aq1 = *reinterpret_cast<const ulonglong2*>(&As[buf][k][ty * 8 + 4]);
            float4 b0 = *reinterpret_cast<const float4*>(&Bs[buf][k][tx * 8]);
            float4 b1 = *reinterpret_cast<const float4*>(&Bs[buf][k][tx * 8 + 4]);
            unsigned long long ap[4] = {aq0.x, aq0.y, aq1.x, aq1.y};
            unsigned long long bd[8] = {dup2(b0.x), dup2(b0.y), dup2(b0.z), dup2(b0.w),
                                        dup2(b1.x), dup2(b1.y), dup2(b1.z), dup2(b1.w)};
#pragma unroll
            for (int ip = 0; ip < 4; ip++)
#pragma unroll
                for (int j = 0; j < 8; j++) fma2(acc2[ip][j], ap[ip], bd[j]);
        }
        __syncthreads();
    }

    float bv[8];
    {
        float4 bias0 = *reinterpret_cast<const float4*>(&bias[bn + tx * 8]);
        float4 bias1 = *reinterpret_cast<const float4*>(&bias[bn + tx * 8 + 4]);
        bv[0] = bias0.x; bv[1] = bias0.y; bv[2] = bias0.z; bv[3] = bias0.w;
        bv[4] = bias1.x; bv[5] = bias1.y; bv[6] = bias1.z; bv[7] = bias1.w;
    }
#pragma unroll
    for (int ip = 0; ip < 4; ip++) {
        float lo[8], hi[8];
#pragma unroll
        for (int j = 0; j < 8; j++) {
            lo[j] = __uint_as_float((unsigned)acc2[ip][j]) + bv[j];
            hi[j] = __uint_as_float((unsigned)(acc2[ip][j] >> 32)) + bv[j];
        }
        int row0 = bm + ty * 8 + 2 * ip;
        float* cp0 = &C[(size_t)row0 * N + bn + tx * 8];
        float* cp1 = cp0 + N;
        *reinterpret_cast<float4*>(cp0)     = make_float4(lo[0], lo[1], lo[2], lo[3]);
        *reinterpret_cast<float4*>(cp0 + 4) = make_float4(lo[4], lo[5], lo[6], lo[7]);
        *reinterpret_cast<float4*>(cp1)     = make_float4(hi[0], hi[1], hi[2], hi[3]);
        *reinterpret_cast<float4*>(cp1 + 4) = make_float4(hi[4], hi[5], hi[6], hi[7]);
    }
}

// ---------------- persistent GRU recurrence: 2 bgs interleaved per CTA ----------------
// 128 CTAs = 4 pairs (bgs 2p, 2p+1) x 32 e-groups of 16 cols. 256 threads.
// Weights (48 rows x 512, shared by both bgs) in smem. Per global step:
// phase A (bg 2p) then phase B (bg 2p+1); cross-SM propagation of each phase's
// h hides under the other phase's compute. h pre-staged one phase ahead.
// Lane = (eL 0..15, ks 0..1): e-column ebase+eL, k half-slice [64w+32ks, +32).
#define RGRID 128
#define WSTR 516
#define WR2 48
#define SM_HA (WR2 * WSTR)              // 24768
#define SM_HB (SM_HA + 4096)
#define SM_PT (SM_HB + 4096)
#define RSMEM_FLOATS (SM_PT + 9216)     // 42176
#define RSMEM_BYTES (RSMEM_FLOATS * 4)  // 168704 B

#define STAGE(stripe, bg) do {                                                 \
    const float4* hb4 = reinterpret_cast<const float4*>(hbuf);                 \
    _Pragma("unroll")                                                          \
    for (int i_ = 0; i_ < 4; i_++) {                                           \
        int f_ = jg + i_ * 32; int b_ = f_ >> 4, c4_ = f_ & 15;                \
        *reinterpret_cast<float4*>(&(stripe)[b_ * 64 + c4_ * 4]) =             \
            hb4[((bg) * 8 + b_) * 128 + 16 * w + c4_];                         \
    }                                                                          \
    __syncwarp();                                                              \
} while (0)

#define DOT(stripe) do {                                                       \
    _Pragma("unroll")                                                          \
    for (int b_ = 0; b_ < 8; b_++) { a0[b_] = 0ULL; a1[b_] = 0ULL; a2[b_] = 0ULL; } \
    _Pragma("unroll 4")                                                        \
    for (int kk_ = 0; kk_ < 8; kk_++) {                                        \
        int kg_ = koff + kk_ * 4;                                              \
        int kl_ = ks * 32 + kk_ * 4;                                           \
        ulonglong2 w0_ = *reinterpret_cast<const ulonglong2*>(wp0 + kg_);      \
        ulonglong2 w1_ = *reinterpret_cast<const ulonglong2*>(wp1 + kg_);      \
        ulonglong2 w2_ = *reinterpret_cast<const ulonglong2*>(wp2 + kg_);      \
        _Pragma("unroll")                                                      \
        for (int b_ = 0; b_ < 8; b_++) {                                       \
            ulonglong2 h2_ = *reinterpret_cast<const ulonglong2*>((stripe) + b_ * 64 + kl_); \
            fma2(a0[b_], h2_.x, w0_.x); fma2(a0[b_], h2_.y, w0_.y);            \
            fma2(a1[b_], h2_.x, w1_.x); fma2(a1[b_], h2_.y, w1_.y);            \
            fma2(a2[b_], h2_.x, w2_.x); fma2(a2[b_], h2_.y, w2_.y);            \
        }                                                                      \
    }                                                                          \
} while (0)

#define STORE_PART() do {                                                      \
    _Pragma("unroll")                                                          \
    for (int b_ = 0; b_ < 8; b_++) {                                           \
        sh_pt[((w * 3 + 0) * 8 + b_) * 48 + jg] = f32x2_sum(a0[b_]);           \
        sh_pt[((w * 3 + 1) * 8 + b_) * 48 + jg] = f32x2_sum(a1[b_]);           \
        sh_pt[((w * 3 + 2) * 8 + b_) * 48 + jg] = f32x2_sum(a2[b_]);           \
    }                                                                          \
} while (0)

#define REDUCE_GATES(xr_, xz_, xn_, hprev_, len_, bglob_, hnew_) do {          \
    float s0_ = 0.f, s1_ = 0.f, s2_ = 0.f;                                     \
    _Pragma("unroll")                                                          \
    for (int ww_ = 0; ww_ < 8; ww_++) {                                        \
        _Pragma("unroll")                                                      \
        for (int kq_ = 0; kq_ < 2; kq_++) {                                    \
            int o_ = kq_ * 16 + ee;                                            \
            s0_ += sh_pt[((ww_ * 3 + 0) * 8 + bb) * 48 + o_];                  \
            s1_ += sh_pt[((ww_ * 3 + 1) * 8 + bb) * 48 + o_];                  \
            s2_ += sh_pt[((ww_ * 3 + 2) * 8 + bb) * 48 + o_];                  \
        }                                                                      \
    }                                                                          \
    float hr_ = s0_ + bh0, hz_ = s1_ + bh1, hn_ = s2_ + bh2;                   \
    float r_ = __frcp_rn(1.f + __expf(-((xr_) + hr_)));                        \
    float z_ = __frcp_rn(1.f + __expf(-((xz_) + hz_)));                        \
    float te_ = __expf(2.f * ((xn_) + r_ * hn_));                              \
    float n_ = (te_ - 1.f) * __frcp_rn(te_ + 1.f);                             \
    bool m_ = (t < (len_));                                                    \
    (hnew_) = m_ ? ((1.f - z_) * n_ + z_ * (hprev_)) : (hprev_);               \
    (hprev_) = (hnew_);                                                        \
    hbuf[(bglob_) * E_SZ + ebase + ee] = (hnew_);                              \
    ymask = m_;                                                                \
} while (0)

__global__ __launch_bounds__(256, 1) void gru_recur_kernel(
    const float* __restrict__ xproj,
    const float* __restrict__ Whh,
    const float* __restrict__ bhh,
    const int* __restrict__ lens,
    float* __restrict__ hbuf,
    float* __restrict__ ybuf,
    float* __restrict__ finals,
    int epoch)
{
    extern __shared__ float smem[];
    float* sh_w  = smem;
    float* sh_hA = smem + SM_HA;
    float* sh_hB = smem + SM_HB;
    float* sh_pt = smem + SM_PT;

    const int tid = threadIdx.x;
    const int cta = blockIdx.x;
    const int p  = cta >> 5;          // pair 0..3
    const int eg = cta & 31;          // e-group 0..31
    const int ebase = eg * 16;
    const int w = tid >> 5;
    const int jg = tid & 31;
    const int eL = jg & 15;
    const int ks = jg >> 4;
    const int bgA = 2 * p, bgB = 2 * p + 1;

    // load 48 weight rows (row j = eL*3 + gate), float4, stride WSTR
    for (int idx = tid; idx < WR2 * (E_SZ / 4); idx += 256) {
        int j = idx >> 7;
        int kq = (idx & 127) << 2;
        int el = j / 3, g = j - el * 3;
        *reinterpret_cast<float4*>(&sh_w[j * WSTR + kq]) =
            *reinterpret_cast<const float4*>(&Whh[(size_t)(g * E_SZ + ebase + el) * E_SZ + kq]);
    }

    // gate-thread (tid < 128) setup
    int bb = 0, ee = 0, bglobA = 0, bglobB = 0, lenA = 0, lenB = 0;
    float bh0 = 0.f, bh1 = 0.f, bh2 = 0.f;
    if (tid < 128) {
        bb = tid >> 4; ee = tid & 15;
        bglobA = bgA * 8 + bb; bglobB = bgB * 8 + bb;
        bh0 = bhh[0 * E_SZ + ebase + ee];
        bh1 = bhh[1 * E_SZ + ebase + ee];
        bh2 = bhh[2 * E_SZ + ebase + ee];
        lenA = lens[bglobA]; lenB = lens[bglobB];
        hbuf[bglobA * E_SZ + ebase + ee] = 0.f;
        hbuf[bglobB * E_SZ + ebase + ee] = 0.f;
    }
    __syncthreads();
    unsigned* myc = &g_ctr[cta * 2];
    if (tid == 0) { ctr_release_add(&myc[0]); ctr_release_add(&myc[1]); }

    const unsigned base = (unsigned)epoch * (T_SEQ + 1);
    // this warp's producer counters (4 CTAs cover its 64 h-columns; lane polls one)
    unsigned* cA = &g_ctr[((p << 5) + 4 * w + (jg & 3)) * 2 + 0];
    unsigned* cB = cA + 1;

    const float* wp0 = sh_w + (eL * 3 + 0) * WSTR;
    const float* wp1 = wp0 + WSTR;
    const float* wp2 = wp1 + WSTR;
    const int koff = w * 64 + ks * 32;
    float* stA = sh_hA + w * 512;
    float* stB = sh_hB + w * 512;

    unsigned long long a0[8], a1[8], a2[8];
    float hprevA = 0.f, hprevB = 0.f, hnewA = 0.f, hnewB = 0.f;
    float xrA = 0.f, xzA = 0.f, xnA = 0.f, xrB = 0.f, xzB = 0.f, xnB = 0.f;
    bool ymask = false;

    // pre-stage A(0)
    ctr_wait(cA, base + 1);
    __syncwarp();
    STAGE(stA, bgA);

    for (int t = 0; t < T_SEQ; t++) {
        // xp for phase A (overlaps dot A)
        if (tid < 128) {
            const float* xp = xproj + ((size_t)t * B_SZ + bglobA) * G3E + ebase + ee;
            xrA = xp[0]; xzA = xp[E_SZ]; xnA = xp[2 * E_SZ];
        }

        DOT(stA);
        __syncthreads();

        // wait + stage B(t): B's h(t) was published at the end of step t-1
        ctr_wait(cB, base + 1 + (unsigned)t);
        __syncwarp();
        STAGE(stB, bgB);

        STORE_PART();
        __syncthreads();
        if (tid < 128) REDUCE_GATES(xrA, xzA, xnA, hprevA, lenA, bglobA, hnewA);
        __syncthreads();
        if (tid == 0) ctr_release_add(&myc[0]);
        if (tid < 128) {
            ybuf[((size_t)t * B_SZ + bglobA) * E_SZ + ebase + ee] = ymask ? hnewA : 0.f;
            const float* xp = xproj + ((size_t)t * B_SZ + bglobB) * G3E + ebase + ee;
            xrB = xp[0]; xzB = xp[E_SZ]; xnB = xp[2 * E_SZ];
        }

        DOT(stB);
        __syncthreads();

        // pre-stage A(t+1): A's h(t+1) was published in phase A of this step
        if (t + 1 < T_SEQ) {
            ctr_wait(cA, base + 2 + (unsigned)t);
            __syncwarp();
            STAGE(stA, bgA);
        }

        STORE_PART();
        __syncthreads();
        if (tid < 128) REDUCE_GATES(xrB, xzB, xnB, hprevB, lenB, bglobB, hnewB);
        __syncthreads();
        if (tid == 0) ctr_release_add(&myc[1]);
        if (tid < 128)
            ybuf[((size_t)t * B_SZ + bglobB) * E_SZ + ebase + ee] = ymask ? hnewB : 0.f;
    }

    if (tid < 128) {
        finals[bglobA * E_SZ + ebase + ee] = hprevA;
        finals[bglobB * E_SZ + ebase + ee] = hprevB;
    }
}

// ---------------- launch ----------------
extern "C" void kernel_launch(void* const* d_in, const int* in_sizes, int n_in,
                              void* d_out, int out_size) {
    const int*   input_batch = (const int*)d_in[0];
    const int*   lens        = (const int*)d_in[1];
    const float* emb         = (const float*)d_in[2];
    const float* W_ih        = (const float*)d_in[3];
    const float* W_hh        = (const float*)d_in[4];
    const float* b_ih        = (const float*)d_in[5];
    const float* b_hh        = (const float*)d_in[6];
    float* out = (float*)d_out;

    void* p;
    cudaGetSymbolAddress(&p, g_x);     float* gx  = (float*)p;
    cudaGetSymbolAddress(&p, g_xproj); float* gxp = (float*)p;
    cudaGetSymbolAddress(&p, g_h);     float* gh  = (float*)p;

    cudaFuncSetAttribute(gru_recur_kernel,
                         cudaFuncAttributeMaxDynamicSharedMemorySize, RSMEM_BYTES);

    const int M = M_ROWS;
    const size_t out_x_elems = (size_t)T_SEQ * B_SZ * E_SZ;
    float* finals0 = out + out_x_elems;
    float* finals1 = out + out_x_elems + B_SZ * E_SZ;

    {
        int total = T_SEQ * B_SZ * (E_SZ / 4);
        embed_kernel<<<(total + 255) / 256, 256>>>(input_batch, emb, gx);
    }
    gemm_nt_bias<<<dim3(G3E / BN, M / BM), 256>>>(gx, W_ih, b_ih, gxp, M, G3E, E_SZ);
    gru_recur_kernel<<<RGRID, 256, RSMEM_BYTES>>>(gxp, W_hh, b_hh, lens, gh, gx, finals0, 0);
    gemm_nt_bias<<<dim3(G3E / BN, M / BM), 256>>>(gx, W_ih + (size_t)G3E * E_SZ,
                                                  b_ih + G3E, gxp, M, G3E, E_SZ);
    gru_recur_kernel<<<RGRID, 256, RSMEM_BYTES>>>(gxp, W_hh + (size_t)G3E * E_SZ,
                                                  b_hh + G3E, lens, gh, out, finals1, 1);
}